// round 3
// baseline (speedup 1.0000x reference)
#include <cuda_runtime.h>

#define NN   50000
#define NE   800000
#define DIN  96
#define DH   128
#define DOUT 16

typedef unsigned long long ull;

// ---------------- scratch (no allocations allowed) ----------------
__device__ float g_agg1  [NN * DIN];      // 19.2 MB  sum of x[src] at dst
__device__ float g_deg   [NN];            // in-degree (float)
__device__ float g_r     [NN * 32];       // [p | q] = h @ [W2_l | W2_r]
__device__ int   g_cnt   [NN];            // histogram
__device__ int   g_rowptr[NN + 1];        // CSR row pointers
__device__ int   g_cursor[NN];            // scatter cursors
__device__ int   g_esrc  [NE];            // src ids grouped by dst
__device__ int   g_is64;

// ---------------- f32x2 packed helpers (sm_100+) ----------------
__device__ __forceinline__ ull pk(float a, float b) {
    ull r; asm("mov.b64 %0, {%1,%2};" : "=l"(r) : "f"(a), "f"(b)); return r;
}
__device__ __forceinline__ float2 upk(ull a) {
    float2 f; asm("mov.b64 {%0,%1}, %2;" : "=f"(f.x), "=f"(f.y) : "l"(a)); return f;
}
__device__ __forceinline__ ull fma2(ull a, ull b, ull c) {
    ull d; asm("fma.rn.f32x2 %0, %1, %2, %3;" : "=l"(d) : "l"(a), "l"(b), "l"(c)); return d;
}

// ---------------- dtype detection for edge_index ----------------
__global__ void k_detect(const int* __restrict__ ei) {
    int all0 = 1;
#pragma unroll 1
    for (int i = 1; i < 256; i += 2) all0 &= (ei[i] == 0);
    g_is64 = all0;
}

// ---------------- CSR build: histogram ----------------
__global__ void k_hist(const int* __restrict__ ei32,
                       const long long* __restrict__ ei64) {
    int e = blockIdx.x * blockDim.x + threadIdx.x;
    if (e >= NE) return;
    int dst = g_is64 ? (int)ei64[NE + e] : ei32[NE + e];
    atomicAdd(&g_cnt[dst], 1);
}

// ---------------- CSR build: single-block scan of 50k counters ----------------
// 1024 threads, 49 elements each (two-pass per thread, no local array)
__global__ void __launch_bounds__(1024) k_scan() {
    __shared__ int ssum[1024];
    const int t    = threadIdx.x;
    const int base = t * 49;

    int run = 0;
#pragma unroll 1
    for (int i = 0; i < 49; i++) {
        int idx = base + i;
        run += (idx < NN) ? g_cnt[idx] : 0;
    }
    ssum[t] = run;
    __syncthreads();
    // Hillis-Steele inclusive scan
    for (int off = 1; off < 1024; off <<= 1) {
        int v = (t >= off) ? ssum[t - off] : 0;
        __syncthreads();
        ssum[t] += v;
        __syncthreads();
    }
    int excl = (t == 0) ? 0 : ssum[t - 1];
#pragma unroll 1
    for (int i = 0; i < 49; i++) {
        int idx = base + i;
        if (idx <= NN) {
            g_rowptr[idx] = excl;
            if (idx < NN) g_cursor[idx] = excl;
        }
        if (idx < NN) excl += g_cnt[idx];
    }
}

// ---------------- CSR build: scatter src ids grouped by dst ----------------
__global__ void k_scatter(const int* __restrict__ ei32,
                          const long long* __restrict__ ei64) {
    int e = blockIdx.x * blockDim.x + threadIdx.x;
    if (e >= NE) return;
    int src, dst;
    if (g_is64) { src = (int)ei64[e]; dst = (int)ei64[NE + e]; }
    else        { src = ei32[e];      dst = ei32[NE + e]; }
    int pos = atomicAdd(&g_cursor[dst], 1);
    g_esrc[pos] = src;
}

// ---------------- layer-1 aggregation: gather, no atomics ----------------
// one warp per node; 3 coalesced floats per lane cover 96 dims
__global__ void __launch_bounds__(256) k_aggx(const float* __restrict__ x) {
    const int lane = threadIdx.x & 31;
    const int n    = blockIdx.x * 8 + (threadIdx.x >> 5);
    if (n >= NN) return;
    const int beg = g_rowptr[n];
    const int end = g_rowptr[n + 1];

    float a0 = 0.f, a1 = 0.f, a2 = 0.f;
    int i = beg;
#pragma unroll 1
    for (; i + 1 < end; i += 2) {
        int s0 = g_esrc[i], s1 = g_esrc[i + 1];
        const float* x0 = x + (size_t)s0 * DIN;
        const float* x1 = x + (size_t)s1 * DIN;
        a0 += x0[lane]      + x1[lane];
        a1 += x0[lane + 32] + x1[lane + 32];
        a2 += x0[lane + 64] + x1[lane + 64];
    }
    if (i < end) {
        const float* x0 = x + (size_t)g_esrc[i] * DIN;
        a0 += x0[lane]; a1 += x0[lane + 32]; a2 += x0[lane + 64];
    }
    float* o = g_agg1 + (size_t)n * DIN;
    o[lane] = a0; o[lane + 32] = a1; o[lane + 64] = a2;
    if (lane == 0) g_deg[n] = (float)(end - beg);
}

// ---------------- fused layer-1 GEMM + layer-2 projection ----------------
__global__ void __launch_bounds__(128) k_fused(
        const float* __restrict__ x,
        const float* __restrict__ W1l,
        const float* __restrict__ b1,
        const float* __restrict__ W1r,
        const float* __restrict__ W2l,
        const float* __restrict__ W2r) {

    __shared__ ulonglong2 aspv[DIN][2];
    __shared__ ulonglong2 xspv[DIN][2];
    __shared__ ull        hsT [4][DH];
    __shared__ float      wsT [32][132];
    __shared__ float      inv [8];

    const int tid  = threadIdx.x;
    const int row0 = blockIdx.x * 8;

    if (tid < 8) inv[tid] = 1.0f / fmaxf(g_deg[row0 + tid], 1.0f);

    for (int i = tid; i < DH * DOUT; i += 128) {
        int k = i >> 4, j = i & 15;
        wsT[j][k]      = W2l[i];
        wsT[j + 16][k] = W2r[i];
    }
    __syncthreads();

    {
        float* aspf = (float*)aspv;
        float* xspf = (float*)xspv;
        for (int idx = tid; idx < 8 * DIN; idx += 128) {
            int r = idx / DIN, k = idx - r * DIN;
            size_t g = (size_t)(row0 + r) * DIN + k;
            aspf[k * 8 + r] = g_agg1[g] * inv[r];
            xspf[k * 8 + r] = x[g];
        }
    }
    __syncthreads();

    const int j = tid;
    ull acc[4];
    {
        float bj = b1[j];
        ull b2p = pk(bj, bj);
#pragma unroll
        for (int p = 0; p < 4; p++) acc[p] = b2p;
    }

#pragma unroll 2
    for (int k = 0; k < DIN; k++) {
        float wl = W1l[k * DH + j];
        float wr = W1r[k * DH + j];
        ull wl2 = pk(wl, wl);
        ull wr2 = pk(wr, wr);
#pragma unroll
        for (int i = 0; i < 2; i++) {
            ulonglong2 av = aspv[k][i];
            ulonglong2 xv = xspv[k][i];
            acc[2*i]   = fma2(av.x, wl2, acc[2*i]);
            acc[2*i]   = fma2(xv.x, wr2, acc[2*i]);
            acc[2*i+1] = fma2(av.y, wl2, acc[2*i+1]);
            acc[2*i+1] = fma2(xv.y, wr2, acc[2*i+1]);
        }
    }

#pragma unroll
    for (int p = 0; p < 4; p++) {
        float2 f = upk(acc[p]);
        hsT[p][j] = pk(fmaxf(f.x, 0.0f), fmaxf(f.y, 0.0f));
    }
    __syncthreads();

    const int c  = tid & 31;
    const int rp = tid >> 5;
    const ulonglong2* hrow = (const ulonglong2*)hsT[rp];
    const float4*     wrow = (const float4*)wsT[c];

    ull acc2 = 0;
#pragma unroll 8
    for (int k4 = 0; k4 < DH / 4; k4++) {
        float4     w4  = wrow[k4];
        ulonglong2 h01 = hrow[2*k4];
        ulonglong2 h23 = hrow[2*k4+1];
        acc2 = fma2(h01.x, pk(w4.x, w4.x), acc2);
        acc2 = fma2(h01.y, pk(w4.y, w4.y), acc2);
        acc2 = fma2(h23.x, pk(w4.z, w4.z), acc2);
        acc2 = fma2(h23.y, pk(w4.w, w4.w), acc2);
    }
    float2 o2 = upk(acc2);
    g_r[(size_t)(row0 + 2*rp)     * 32 + c] = o2.x;
    g_r[(size_t)(row0 + 2*rp + 1) * 32 + c] = o2.y;
}

// ---------------- layer-2 aggregation + softmax epilogue (fused) ----------------
// one warp per node; 2 edges per iteration across half-warps
__global__ void __launch_bounds__(256) k_aggp_fin(const float* __restrict__ b2,
                                                  float* __restrict__ out) {
    const int lane = threadIdx.x & 31;
    const int n    = blockIdx.x * 8 + (threadIdx.x >> 5);
    if (n >= NN) return;
    const int beg = g_rowptr[n];
    const int end = g_rowptr[n + 1];
    const int c   = lane & 15;

    float acc = 0.f;
#pragma unroll 1
    for (int i = beg; i < end; i += 2) {
        int idx = i + (lane >> 4);
        if (idx < end) {
            int s = g_esrc[idx];
            acc += g_r[(size_t)s * 32 + c];
        }
    }
    acc += __shfl_down_sync(0xffffffffu, acc, 16);

    float invd = 1.0f / fmaxf((float)(end - beg), 1.0f);
    float val  = acc * invd + b2[c] + g_r[(size_t)n * 32 + 16 + c];

    // width-16 softmax
    float mx = val;
#pragma unroll
    for (int o = 8; o > 0; o >>= 1) mx = fmaxf(mx, __shfl_xor_sync(0xffffffffu, mx, o, 16));
    float e = __expf(val - mx);
    float s = e;
#pragma unroll
    for (int o = 8; o > 0; o >>= 1) s += __shfl_xor_sync(0xffffffffu, s, o, 16);

    if (lane < 16) out[(size_t)n * DOUT + c] = e / s;
}

// ---------------- launch ----------------
extern "C" void kernel_launch(void* const* d_in, const int* in_sizes, int n_in,
                              void* d_out, int out_size) {
    const float*     x    = (const float*)d_in[0];
    const int*       ei32 = (const int*)d_in[1];
    const long long* ei64 = (const long long*)d_in[1];
    const float*     W1l  = (const float*)d_in[2];
    const float*     b1   = (const float*)d_in[3];
    const float*     W1r  = (const float*)d_in[4];
    const float*     W2l  = (const float*)d_in[5];
    const float*     b2   = (const float*)d_in[6];
    const float*     W2r  = (const float*)d_in[7];
    float* out = (float*)d_out;

    void* cntp;
    cudaGetSymbolAddress(&cntp, g_cnt);
    cudaMemsetAsync(cntp, 0, sizeof(int) * NN, 0);

    k_detect <<<1, 1>>>(ei32);
    k_hist   <<<(NE + 255) / 256, 256>>>(ei32, ei64);
    k_scan   <<<1, 1024>>>();
    k_scatter<<<(NE + 255) / 256, 256>>>(ei32, ei64);
    k_aggx   <<<(NN + 7) / 8, 256>>>(x);
    k_fused  <<<NN / 8, 128>>>(x, W1l, b1, W1r, W2l, W2r);
    k_aggp_fin<<<(NN + 7) / 8, 256>>>(b2, out);
}

// round 4
// speedup vs baseline: 1.1856x; 1.1856x over previous
#include <cuda_runtime.h>
#include <cstdint>

#define NN   50000
#define NE   800000
#define DIN  96
#define DH   128
#define DOUT 16

typedef unsigned long long ull;

// ---------------- scratch (no allocations allowed) ----------------
__device__ __align__(16) float g_agg1[NN * DIN];   // sum of x[src] at dst
__device__ float g_deg [NN];
__device__ __align__(16) float g_r   [NN * 32];    // [p | q] = h @ [W2_l | W2_r]
__device__ __align__(16) float g_agg2[NN * DOUT];  // sum of p[src] at dst
__device__ int   g_is64;

// ---------------- helpers ----------------
__device__ __forceinline__ ull pk(float a, float b) {
    ull r; asm("mov.b64 %0, {%1,%2};" : "=l"(r) : "f"(a), "f"(b)); return r;
}
__device__ __forceinline__ float2 upk(ull a) {
    float2 f; asm("mov.b64 {%0,%1}, %2;" : "=f"(f.x), "=f"(f.y) : "l"(a)); return f;
}
__device__ __forceinline__ ull fma2(ull a, ull b, ull c) {
    ull d; asm("fma.rn.f32x2 %0, %1, %2, %3;" : "=l"(d) : "l"(a), "l"(b), "l"(c)); return d;
}
__device__ __forceinline__ uint32_t smem_u32(const void* p) {
    uint32_t a;
    asm("{ .reg .u64 t; cvta.to.shared.u64 t, %1; cvt.u32.u64 %0, t; }" : "=r"(a) : "l"(p));
    return a;
}
__device__ __forceinline__ void tma_reduce_add_f32(float* gdst, uint32_t ssrc, int bytes) {
    asm volatile("cp.reduce.async.bulk.global.shared::cta.bulk_group.add.f32 [%0], [%1], %2;"
                 :: "l"(gdst), "r"(ssrc), "r"(bytes) : "memory");
}

// ---------------- dtype detection for edge_index ----------------
__global__ void k_detect(const int* __restrict__ ei) {
    int all0 = 1;
#pragma unroll 1
    for (int i = 1; i < 256; i += 2) all0 &= (ei[i] == 0);
    g_is64 = all0;
}

// ---------------- layer-1 aggregation via TMA bulk reduce ----------------
// 64 edges per block: stage x[src] rows in smem, one cp.reduce per edge.
#define EB1 64
__global__ void __launch_bounds__(256) k_aggx_tma(const int* __restrict__ ei32,
                                                  const long long* __restrict__ ei64,
                                                  const float* __restrict__ x) {
    __shared__ __align__(16) float rows[EB1][DIN];   // 24 KB
    __shared__ int ssrc[EB1];
    __shared__ int sdst[EB1];

    const int tid = threadIdx.x;
    const int e0  = blockIdx.x * EB1;

    if (tid < EB1) {
        int e = e0 + tid;
        int src, dst;
        if (g_is64) { src = (int)ei64[e]; dst = (int)ei64[NE + e]; }
        else        { src = ei32[e];      dst = ei32[NE + e]; }
        ssrc[tid] = src;
        sdst[tid] = dst;
        atomicAdd(&g_deg[dst], 1.0f);
    }
    __syncthreads();

    // stage 64 rows x 24 float4 = 1536 vec-loads, 6 per thread, coalesced per row
#pragma unroll
    for (int i = tid; i < EB1 * 24; i += 256) {
        int r = i / 24, c = i - r * 24;
        ((float4*)rows[r])[c] = ((const float4*)(x + (size_t)ssrc[r] * DIN))[c];
    }
    asm volatile("fence.proxy.async.shared::cta;" ::: "memory");
    __syncthreads();

    if (tid < EB1) {
        tma_reduce_add_f32(g_agg1 + (size_t)sdst[tid] * DIN, smem_u32(rows[tid]), DIN * 4);
        asm volatile("cp.async.bulk.commit_group;" ::: "memory");
        asm volatile("cp.async.bulk.wait_group 0;" ::: "memory");
    }
}

// ---------------- fused layer-1 GEMM + layer-2 projection (unchanged, R2) ----------------
__global__ void __launch_bounds__(128) k_fused(
        const float* __restrict__ x,
        const float* __restrict__ W1l,
        const float* __restrict__ b1,
        const float* __restrict__ W1r,
        const float* __restrict__ W2l,
        const float* __restrict__ W2r) {

    __shared__ ulonglong2 aspv[DIN][2];
    __shared__ ulonglong2 xspv[DIN][2];
    __shared__ ull        hsT [4][DH];
    __shared__ float      wsT [32][132];
    __shared__ float      inv [8];

    const int tid  = threadIdx.x;
    const int row0 = blockIdx.x * 8;

    if (tid < 8) inv[tid] = 1.0f / fmaxf(g_deg[row0 + tid], 1.0f);

    for (int i = tid; i < DH * DOUT; i += 128) {
        int k = i >> 4, j = i & 15;
        wsT[j][k]      = W2l[i];
        wsT[j + 16][k] = W2r[i];
    }
    __syncthreads();

    {
        float* aspf = (float*)aspv;
        float* xspf = (float*)xspv;
        for (int idx = tid; idx < 8 * DIN; idx += 128) {
            int r = idx / DIN, k = idx - r * DIN;
            size_t g = (size_t)(row0 + r) * DIN + k;
            aspf[k * 8 + r] = g_agg1[g] * inv[r];
            xspf[k * 8 + r] = x[g];
        }
    }
    __syncthreads();

    const int j = tid;
    ull acc[4];
    {
        float bj = b1[j];
        ull b2p = pk(bj, bj);
#pragma unroll
        for (int p = 0; p < 4; p++) acc[p] = b2p;
    }

#pragma unroll 2
    for (int k = 0; k < DIN; k++) {
        float wl = W1l[k * DH + j];
        float wr = W1r[k * DH + j];
        ull wl2 = pk(wl, wl);
        ull wr2 = pk(wr, wr);
#pragma unroll
        for (int i = 0; i < 2; i++) {
            ulonglong2 av = aspv[k][i];
            ulonglong2 xv = xspv[k][i];
            acc[2*i]   = fma2(av.x, wl2, acc[2*i]);
            acc[2*i]   = fma2(xv.x, wr2, acc[2*i]);
            acc[2*i+1] = fma2(av.y, wl2, acc[2*i+1]);
            acc[2*i+1] = fma2(xv.y, wr2, acc[2*i+1]);
        }
    }

#pragma unroll
    for (int p = 0; p < 4; p++) {
        float2 f = upk(acc[p]);
        hsT[p][j] = pk(fmaxf(f.x, 0.0f), fmaxf(f.y, 0.0f));
    }
    __syncthreads();

    const int c  = tid & 31;
    const int rp = tid >> 5;
    const ulonglong2* hrow = (const ulonglong2*)hsT[rp];
    const float4*     wrow = (const float4*)wsT[c];

    ull acc2 = 0;
#pragma unroll 8
    for (int k4 = 0; k4 < DH / 4; k4++) {
        float4     w4  = wrow[k4];
        ulonglong2 h01 = hrow[2*k4];
        ulonglong2 h23 = hrow[2*k4+1];
        acc2 = fma2(h01.x, pk(w4.x, w4.x), acc2);
        acc2 = fma2(h01.y, pk(w4.y, w4.y), acc2);
        acc2 = fma2(h23.x, pk(w4.z, w4.z), acc2);
        acc2 = fma2(h23.y, pk(w4.w, w4.w), acc2);
    }
    float2 o2 = upk(acc2);
    g_r[(size_t)(row0 + 2*rp)     * 32 + c] = o2.x;
    g_r[(size_t)(row0 + 2*rp + 1) * 32 + c] = o2.y;
}

// ---------------- layer-2 aggregation via TMA bulk reduce ----------------
// 256 edges per block: stage 16-float p rows, one 64B cp.reduce per edge.
#define EB2 256
__global__ void __launch_bounds__(256) k_aggp_tma(const int* __restrict__ ei32,
                                                  const long long* __restrict__ ei64) {
    __shared__ __align__(16) float rows[EB2][DOUT];  // 16 KB
    __shared__ int ssrc[EB2];
    __shared__ int sdst[EB2];

    const int tid = threadIdx.x;
    const int e0  = blockIdx.x * EB2;

    {
        int e = e0 + tid;
        int src, dst;
        if (g_is64) { src = (int)ei64[e]; dst = (int)ei64[NE + e]; }
        else        { src = ei32[e];      dst = ei32[NE + e]; }
        ssrc[tid] = src;
        sdst[tid] = dst;
    }
    __syncthreads();

    // stage 256 rows x 4 float4 = 1024 vec-loads, 4 per thread
#pragma unroll
    for (int i = tid; i < EB2 * 4; i += 256) {
        int r = i >> 2, c = i & 3;
        ((float4*)rows[r])[c] = ((const float4*)(g_r + (size_t)ssrc[r] * 32))[c];
    }
    asm volatile("fence.proxy.async.shared::cta;" ::: "memory");
    __syncthreads();

    tma_reduce_add_f32(g_agg2 + (size_t)sdst[tid] * DOUT, smem_u32(rows[tid]), DOUT * 4);
    asm volatile("cp.async.bulk.commit_group;" ::: "memory");
    asm volatile("cp.async.bulk.wait_group 0;" ::: "memory");
}

// ---------------- epilogue: softmax(agg2/deg + b2 + q) ----------------
__global__ void k_finalize(const float* __restrict__ b2,
                           float* __restrict__ out) {
    int row = blockIdx.x * blockDim.x + threadIdx.x;
    if (row >= NN) return;
    float inv = 1.0f / fmaxf(g_deg[row], 1.0f);

    float v[DOUT];
    float mx = -1e30f;
#pragma unroll
    for (int j = 0; j < DOUT; j++) {
        v[j] = g_agg2[(size_t)row * DOUT + j] * inv + b2[j]
             + g_r[(size_t)row * 32 + 16 + j];
        mx = fmaxf(mx, v[j]);
    }
    float s = 0.f;
#pragma unroll
    for (int j = 0; j < DOUT; j++) {
        v[j] = __expf(v[j] - mx);
        s += v[j];
    }
    float is = 1.0f / s;
#pragma unroll
    for (int j = 0; j < DOUT; j++)
        out[(size_t)row * DOUT + j] = v[j] * is;
}

// ---------------- launch ----------------
extern "C" void kernel_launch(void* const* d_in, const int* in_sizes, int n_in,
                              void* d_out, int out_size) {
    const float*     x    = (const float*)d_in[0];
    const int*       ei32 = (const int*)d_in[1];
    const long long* ei64 = (const long long*)d_in[1];
    const float*     W1l  = (const float*)d_in[2];
    const float*     b1   = (const float*)d_in[3];
    const float*     W1r  = (const float*)d_in[4];
    const float*     W2l  = (const float*)d_in[5];
    const float*     b2   = (const float*)d_in[6];
    const float*     W2r  = (const float*)d_in[7];
    float* out = (float*)d_out;

    void *agg1p, *degp, *agg2p;
    cudaGetSymbolAddress(&agg1p, g_agg1);
    cudaGetSymbolAddress(&degp,  g_deg);
    cudaGetSymbolAddress(&agg2p, g_agg2);
    cudaMemsetAsync(agg1p, 0, sizeof(float) * NN * DIN, 0);
    cudaMemsetAsync(degp,  0, sizeof(float) * NN, 0);
    cudaMemsetAsync(agg2p, 0, sizeof(float) * NN * DOUT, 0);

    k_detect   <<<1, 1>>>(ei32);
    k_aggx_tma <<<NE / EB1, 256>>>(ei32, ei64, x);
    k_fused    <<<NN / 8, 128>>>(x, W1l, b1, W1r, W2l, W2r);
    k_aggp_tma <<<NE / EB2, 256>>>(ei32, ei64);
    k_finalize <<<(NN + 127) / 128, 128>>>(b2, out);
}